// round 3
// baseline (speedup 1.0000x reference)
#include <cuda_runtime.h>
#include <cstdint>

#define NS 512
#define NC 128
#define ND 640
#define TT 256
#define NBLK 148

// ---------------- persistent device state (no allocation allowed) ----------------
__device__ __align__(16) float g_Ft[ND * NS];   // F^T  (640 x 512)
__device__ __align__(16) float g_V [NS * NS];   // carry V
__device__ __align__(16) float g_FV[ND * NS];   // F^T V
__device__ __align__(16) float g_Q [ND * ND];   // Q
__device__ __align__(16) float g_K [NC * NS];   // K
__device__ __align__(16) float g_X [2][NC * NC]; // Newton ping-pong for Quu^-1
__device__ float g_q[ND];
__device__ float g_w[NS];
__device__ float g_v[NS];
__device__ float g_k[NC];
__device__ float g_cst;
__device__ unsigned g_arrive;
__device__ volatile unsigned g_gen;

// ---------------- grid-wide barrier (all NBLK blocks resident, 1/SM) -------------
__device__ __forceinline__ void gsync() {
    __syncthreads();
    if (threadIdx.x == 0) {
        unsigned gen = g_gen;
        __threadfence();
        if (atomicAdd(&g_arrive, 1u) == gridDim.x - 1) {
            g_arrive = 0;
            __threadfence();
            g_gen = gen + 1;
        } else {
            while (g_gen == gen) { __nanosleep(64); }
        }
        __threadfence();
    }
    __syncthreads();
}

// ---------------- packed f32x2 FMA helpers ---------------------------------------
union UF2 { unsigned long long u; float2 f; };

__device__ __forceinline__ void ffma2(unsigned long long& d,
                                      unsigned long long a, unsigned long long b) {
    asm("fma.rn.f32x2 %0, %1, %2, %0;" : "+l"(d) : "l"(a), "l"(b));
}
__device__ __forceinline__ unsigned long long dup2(float x) {
    unsigned long long r; unsigned xi = __float_as_uint(x);
    asm("mov.b64 %0, {%1, %1};" : "=l"(r) : "r"(xi));
    return r;
}

// ---------------- 64x64 tile SGEMM (f32x2), D = alpha*A@B (+Cin), optional D2 -----
// smem layout: As_dup[16][132] (A values duplicated pairwise), Bs[16][72]
__device__ __forceinline__ void gemm64(
    const float* __restrict__ A, int lda,
    const float* __restrict__ B, int ldb,
    const float* __restrict__ Cin, int ldc,
    float* __restrict__ D, int ldd,
    float* __restrict__ D2,
    int Ksz, float alpha, int m0, int n0, float* sm)
{
    float* As = sm;               // 16*132 = 2112 floats (row = 528B, 16B-aligned)
    float* Bs = sm + 16 * 132;    // 16*72  = 1152 floats (row = 288B, 16B-aligned)
    const int tid = threadIdx.x;
    const int tx = tid & 15, ty = tid >> 4;
    const int la_m = tid >> 2, la_k = (tid & 3) << 2;
    const int lb_k = tid >> 4, lb_n = (tid & 15) << 2;
    const float* Ap = A + (size_t)(m0 + la_m) * lda + la_k;
    const float* Bp = B + (size_t)lb_k * ldb + n0 + lb_n;
    UF2 acc[4][2];
#pragma unroll
    for (int i = 0; i < 4; i++) { acc[i][0].u = 0ull; acc[i][1].u = 0ull; }
    float4 av = *(const float4*)Ap;
    float4 bv = *(const float4*)Bp;
    for (int k0 = 0; k0 < Ksz; k0 += 16) {
        *(unsigned long long*)&As[(la_k + 0) * 132 + la_m * 2] = dup2(av.x);
        *(unsigned long long*)&As[(la_k + 1) * 132 + la_m * 2] = dup2(av.y);
        *(unsigned long long*)&As[(la_k + 2) * 132 + la_m * 2] = dup2(av.z);
        *(unsigned long long*)&As[(la_k + 3) * 132 + la_m * 2] = dup2(av.w);
        *(float4*)&Bs[lb_k * 72 + lb_n] = bv;
        __syncthreads();
        if (k0 + 16 < Ksz) {
            av = *(const float4*)(Ap + (k0 + 16));
            bv = *(const float4*)(Bp + (size_t)(k0 + 16) * ldb);
        }
#pragma unroll
        for (int kk = 0; kk < 16; kk++) {
            ulonglong2 aA = *(const ulonglong2*)&As[kk * 132 + ty * 8];
            ulonglong2 aB = *(const ulonglong2*)&As[kk * 132 + ty * 8 + 4];
            ulonglong2 bP = *(const ulonglong2*)&Bs[kk * 72 + tx * 4];
            ffma2(acc[0][0].u, aA.x, bP.x); ffma2(acc[0][1].u, aA.x, bP.y);
            ffma2(acc[1][0].u, aA.y, bP.x); ffma2(acc[1][1].u, aA.y, bP.y);
            ffma2(acc[2][0].u, aB.x, bP.x); ffma2(acc[2][1].u, aB.x, bP.y);
            ffma2(acc[3][0].u, aB.y, bP.x); ffma2(acc[3][1].u, aB.y, bP.y);
        }
        __syncthreads();
    }
#pragma unroll
    for (int i = 0; i < 4; i++) {
        int m = m0 + ty * 4 + i;
#pragma unroll
        for (int jp = 0; jp < 2; jp++) {
            int n = n0 + tx * 4 + jp * 2;
            float2 v = acc[i][jp].f;
            float o0 = alpha * v.x, o1 = alpha * v.y;
            if (Cin) { o0 += Cin[(size_t)m * ldc + n]; o1 += Cin[(size_t)m * ldc + n + 1]; }
            D[(size_t)m * ldd + n] = o0; D[(size_t)m * ldd + n + 1] = o1;
            if (D2) { D2[(size_t)m * ldd + n] = o0; D2[(size_t)m * ldd + n + 1] = o1; }
        }
    }
}

// ---------------- Newton-Schulz strip: X' = 2X - X (Quu X) over 4 columns --------
// bid < 32; block bid handles cols J = bid*4. One grid barrier per iteration.
// Qs row stride 20 floats = 80 B (16B-aligned for float4 stores).
__device__ __forceinline__ void newton_strip(const float* __restrict__ Xin,
                                             float* __restrict__ Xout, float* sm)
{
    float* Qs = sm;           // [128][20] = 2560
    float* Xs = sm + 2560;    // [128][4]  = 512
    float* Ts = sm + 3072;    // [128][4]  = 512
    const int tid = threadIdx.x;
    const int J = blockIdx.x * 4;
    for (int i = tid; i < 512; i += 256) {
        int r = i >> 2, jj = i & 3;
        Xs[i] = Xin[r * NC + J + jj];
    }
    __syncthreads();
    const int r = tid >> 1, jh = (tid & 1) * 2;
    float t0 = 0.f, t1 = 0.f;
    for (int k0 = 0; k0 < NC; k0 += 16) {
        for (int i = tid; i < 512; i += 256) {
            int rr = i >> 2, q4 = i & 3;
            *(float4*)&Qs[rr * 20 + q4 * 4] =
                *(const float4*)&g_Q[(size_t)(NS + rr) * ND + NS + k0 + q4 * 4];
        }
        __syncthreads();
#pragma unroll
        for (int kk = 0; kk < 16; kk++) {
            float a = Qs[r * 20 + kk];
            t0 = fmaf(a, Xs[(k0 + kk) * 4 + jh], t0);
            t1 = fmaf(a, Xs[(k0 + kk) * 4 + jh + 1], t1);
        }
        __syncthreads();
    }
    Ts[r * 4 + jh] = t0; Ts[r * 4 + jh + 1] = t1;
    __syncthreads();
    float x0 = 0.f, x1 = 0.f;
    for (int k0 = 0; k0 < NC; k0 += 16) {
        for (int i = tid; i < 512; i += 256) {
            int rr = i >> 2, q4 = i & 3;
            *(float4*)&Qs[rr * 20 + q4 * 4] =
                *(const float4*)&Xin[rr * NC + k0 + q4 * 4];
        }
        __syncthreads();
#pragma unroll
        for (int kk = 0; kk < 16; kk++) {
            float a = Qs[r * 20 + kk];
            x0 = fmaf(a, Ts[(k0 + kk) * 4 + jh], x0);
            x1 = fmaf(a, Ts[(k0 + kk) * 4 + jh + 1], x1);
        }
        __syncthreads();
    }
    Xout[r * NC + J + jh]     = 2.f * Xs[r * 4 + jh]     - x0;
    Xout[r * NC + J + jh + 1] = 2.f * Xs[r * 4 + jh + 1] - x1;
}

// ---------------- the persistent kernel -------------------------------------------
__global__ void __launch_bounds__(256, 1) lqr_kernel(
    const float* __restrict__ F, const float* __restrict__ f,
    const float* __restrict__ C, const float* __restrict__ c,
    float* __restrict__ out)
{
    __shared__ __align__(16) float sm[3600];
    __shared__ float red[264];
    const int bid = blockIdx.x, tid = threadIdx.x, nb = gridDim.x;
    float* outK = out;
    float* outk = outK + (size_t)TT * NC * NS;
    float* outV = outk + (size_t)TT * NC;
    float* outv = outV + (size_t)TT * NS * NS;
    float* outc = outv + (size_t)TT * NS;

    // ---- init: Ft = F^T, V = C[:n,:n], v = c[:n], const = 0 ----
    for (int i = bid * 256 + tid; i < ND * NS; i += nb * 256) {
        int a = i / NS, col = i - a * NS;
        g_Ft[i] = F[(size_t)col * ND + a];
    }
    for (int i = bid * 256 + tid; i < NS * NS; i += nb * 256) {
        int r = i >> 9, cq = i & (NS - 1);
        g_V[i] = C[(size_t)r * ND + cq];
    }
    if (bid == nb - 1) {
        for (int i = tid; i < NS; i += 256) g_v[i] = c[i];
        if (tid == 0) g_cst = 0.f;
    }
    gsync();

    int cur = 0;
    for (int s = 0; s < TT; s++) {
        const int t = TT - 1 - s;

        // ---- Phase A: FV = Ft @ V (80 tiles) ; w = V @ f (leftover blocks) ----
        if (bid < 80) {
            gemm64(g_Ft, NS, g_V, NS, nullptr, 0, g_FV, NS, nullptr,
                   NS, 1.f, (bid >> 3) * 64, (bid & 7) * 64, sm);
        } else {
            int row = (bid - 80) * 8 + (tid >> 5);
            int lane = tid & 31;
            if (row < NS) {
                float ssum = 0.f;
                for (int i = lane; i < NS; i += 32) ssum += g_V[row * NS + i] * f[i];
                for (int o = 16; o; o >>= 1) ssum += __shfl_down_sync(~0u, ssum, o);
                if (!lane) g_w[row] = ssum;
            }
        }
        gsync();

        // ---- Phase B: Q = C + FV @ F (100 tiles) ; q = c + FV@f + Ft@v ----
        if (bid < 100) {
            gemm64(g_FV, NS, F, ND, C, ND, g_Q, ND, nullptr,
                   NS, 1.f, (bid / 10) * 64, (bid % 10) * 64, sm);
        } else {
            int gw = (bid - 100) * 8 + (tid >> 5);
            int lane = tid & 31;
            for (int row = gw; row < ND; row += 384) {
                float ssum = 0.f;
                for (int i = lane; i < NS; i += 32)
                    ssum += g_FV[row * NS + i] * f[i] + g_Ft[row * NS + i] * g_v[i];
                for (int o = 16; o; o >>= 1) ssum += __shfl_down_sync(~0u, ssum, o);
                if (!lane) g_q[row] = c[row] + ssum;
            }
        }
        gsync();

        // ---- Phase C0 (s==0): X0 = I / ||Quu||_inf ----
        if (s == 0) {
            if (bid == 0) {
                float m = 0.f;
                if (tid < NC) {
                    float ssum = 0.f;
                    const float* Qr = &g_Q[(size_t)(NS + tid) * ND + NS];
                    for (int j = 0; j < NC; j++) ssum += fabsf(Qr[j]);
                    m = ssum;
                }
                red[tid] = m; __syncthreads();
                for (int st = 128; st; st >>= 1) {
                    if (tid < st) red[tid] = fmaxf(red[tid], red[tid + st]);
                    __syncthreads();
                }
                float inv = 1.f / red[0];
                __syncthreads();
                for (int i = tid; i < NC * NC; i += 256) {
                    int r2 = i >> 7, c2 = i & 127;
                    g_X[0][i] = (r2 == c2) ? inv : 0.f;
                }
            }
            gsync();
        }

        // ---- Phase C: Newton-Schulz iterations (warm-started) ----
        int niter = (s == 0) ? 20 : ((s < 8) ? 4 : 2);
        for (int it = 0; it < niter; it++) {
            if (bid < 32) newton_strip(g_X[cur], g_X[cur ^ 1], sm);
            cur ^= 1;
            gsync();
        }

        // ---- Phase D: K = -X @ Qux (16 tiles); block 16: k, const ----
        if (bid < 16) {
            gemm64(g_X[cur], NC, g_Q + (size_t)NS * ND, ND, nullptr, 0,
                   g_K, NS, outK + (size_t)t * NC * NS,
                   NC, -1.f, (bid >> 3) * 64, (bid & 7) * 64, sm);
        } else if (bid == 16) {
            float* ksh = sm; float* quk = sm + 132;
            float kv = 0.f;
            if (tid < NC) {
                const float* Xr = g_X[cur] + tid * NC;
                for (int j = 0; j < NC; j++) kv += Xr[j] * g_q[NS + j];
                kv = -kv;
                ksh[tid] = kv; g_k[tid] = kv; outk[(size_t)t * NC + tid] = kv;
            }
            __syncthreads();
            if (tid < NC) {
                float qk = 0.f;
                const float* Qr = &g_Q[(size_t)(NS + tid) * ND + NS];
                for (int j = 0; j < NC; j++) qk = fmaf(Qr[j], ksh[j], qk);
                quk[tid] = qk;
            }
            __syncthreads();
            float p1 = 0.f, p2 = 0.f, p3 = 0.f, p4 = 0.f;
            for (int i = tid; i < NC; i += 256) { p1 += ksh[i] * quk[i]; p2 += ksh[i] * g_q[NS + i]; }
            for (int i = tid; i < NS; i += 256) { p3 += f[i] * g_w[i];   p4 += f[i] * g_v[i]; }
            float parts[4] = {p1, p2, p3, p4};
            float res[4];
            for (int qd = 0; qd < 4; qd++) {
                red[tid] = parts[qd]; __syncthreads();
                for (int st = 128; st; st >>= 1) {
                    if (tid < st) red[tid] += red[tid + st];
                    __syncthreads();
                }
                res[qd] = red[0]; __syncthreads();
            }
            if (tid == 0) {
                float cn = g_cst + 0.5f * res[0] + res[1] + 0.5f * res[2] + res[3];
                g_cst = cn;
                outc[t] = cn;
            }
        }
        gsync();

        // ---- Phase E: Vn = Qxx + Qxu @ K (64 tiles); vn = qx + Qxu @ k ----
        if (bid < 64) {
            gemm64(g_Q + NS, ND, g_K, NS, g_Q, ND, g_V, NS,
                   outV + (size_t)t * NS * NS,
                   NC, 1.f, (bid >> 3) * 64, (bid & 7) * 64, sm);
        } else {
            int row = (bid - 64) * 8 + (tid >> 5);
            int lane = tid & 31;
            if (row < NS) {
                float ssum = 0.f;
                for (int i = lane; i < NC; i += 32)
                    ssum += g_Q[(size_t)row * ND + NS + i] * g_k[i];
                for (int o = 16; o; o >>= 1) ssum += __shfl_down_sync(~0u, ssum, o);
                if (!lane) {
                    float val = g_q[row] + ssum;
                    g_v[row] = val;
                    outv[(size_t)t * NS + row] = val;
                }
            }
        }
        gsync();
    }
}

// ---------------- host -------------------------------------------------------------
extern "C" void kernel_launch(void* const* d_in, const int* in_sizes, int n_in,
                              void* d_out, int out_size) {
    (void)in_sizes; (void)n_in; (void)out_size;
    const float* F = (const float*)d_in[0];
    const float* f = (const float*)d_in[1];
    const float* C = (const float*)d_in[2];
    const float* c = (const float*)d_in[3];
    lqr_kernel<<<NBLK, 256>>>(F, f, C, c, (float*)d_out);
}

// round 6
// speedup vs baseline: 1.5581x; 1.5581x over previous
#include <cuda_runtime.h>
#include <cstdint>

#define NS 512
#define NC 128
#define ND 640
#define TT 256
#define NBLK 148

// ---------------- persistent device state (no allocation allowed) ----------------
__device__ __align__(16) float g_Ft[ND * NS];   // F^T  (640 x 512)
__device__ __align__(16) float g_V [NS * NS];   // carry V
__device__ __align__(16) float g_FV[ND * NS];   // F^T V
__device__ __align__(16) float g_Q [ND * ND];   // Q
__device__ __align__(16) float g_K [NC * NS];   // K
__device__ __align__(16) float g_X [2][NC * NC]; // Newton ping-pong for Quu^-1
__device__ float g_q[ND];
__device__ float g_w[NS];
__device__ float g_v[NS];
__device__ float g_k[NC];
__device__ float g_cst;
__device__ unsigned g_arrive;
__device__ volatile unsigned g_gen;

// ---------------- grid-wide barrier (all NBLK blocks resident, 1/SM) -------------
__device__ __forceinline__ void gsync() {
    __syncthreads();
    if (threadIdx.x == 0) {
        unsigned gen = g_gen;
        __threadfence();
        if (atomicAdd(&g_arrive, 1u) == gridDim.x - 1) {
            g_arrive = 0;
            __threadfence();
            g_gen = gen + 1;
        } else {
            while (g_gen == gen) { __nanosleep(64); }
        }
        __threadfence();
    }
    __syncthreads();
}

// ---------------- packed f32x2 FMA helpers ---------------------------------------
union UF2 { unsigned long long u; float2 f; };

__device__ __forceinline__ void ffma2(unsigned long long& d,
                                      unsigned long long a, unsigned long long b) {
    asm("fma.rn.f32x2 %0, %1, %2, %0;" : "+l"(d) : "l"(a), "l"(b));
}
__device__ __forceinline__ unsigned long long dup2(float x) {
    unsigned long long r; unsigned xi = __float_as_uint(x);
    asm("mov.b64 %0, {%1, %1};" : "=l"(r) : "r"(xi));
    return r;
}

// ---------------- 64x64 tile SGEMM (f32x2), D = alpha*A@B (+Cin), optional D2 -----
// smem layout: As_dup[16][132] (A values duplicated pairwise), Bs[16][72]
__device__ __forceinline__ void gemm64(
    const float* __restrict__ A, int lda,
    const float* __restrict__ B, int ldb,
    const float* __restrict__ Cin, int ldc,
    float* __restrict__ D, int ldd,
    float* __restrict__ D2,
    int Ksz, float alpha, int m0, int n0, float* sm)
{
    float* As = sm;               // 16*132 = 2112 floats (row = 528B, 16B-aligned)
    float* Bs = sm + 16 * 132;    // 16*72  = 1152 floats (row = 288B, 16B-aligned)
    const int tid = threadIdx.x;
    const int tx = tid & 15, ty = tid >> 4;
    const int la_m = tid >> 2, la_k = (tid & 3) << 2;
    const int lb_k = tid >> 4, lb_n = (tid & 15) << 2;
    const float* Ap = A + (size_t)(m0 + la_m) * lda + la_k;
    const float* Bp = B + (size_t)lb_k * ldb + n0 + lb_n;
    UF2 acc[4][2];
#pragma unroll
    for (int i = 0; i < 4; i++) { acc[i][0].u = 0ull; acc[i][1].u = 0ull; }
    float4 av = *(const float4*)Ap;
    float4 bv = *(const float4*)Bp;
    for (int k0 = 0; k0 < Ksz; k0 += 16) {
        *(unsigned long long*)&As[(la_k + 0) * 132 + la_m * 2] = dup2(av.x);
        *(unsigned long long*)&As[(la_k + 1) * 132 + la_m * 2] = dup2(av.y);
        *(unsigned long long*)&As[(la_k + 2) * 132 + la_m * 2] = dup2(av.z);
        *(unsigned long long*)&As[(la_k + 3) * 132 + la_m * 2] = dup2(av.w);
        *(float4*)&Bs[lb_k * 72 + lb_n] = bv;
        __syncthreads();
        if (k0 + 16 < Ksz) {
            av = *(const float4*)(Ap + (k0 + 16));
            bv = *(const float4*)(Bp + (size_t)(k0 + 16) * ldb);
        }
#pragma unroll
        for (int kk = 0; kk < 16; kk++) {
            ulonglong2 aA = *(const ulonglong2*)&As[kk * 132 + ty * 8];
            ulonglong2 aB = *(const ulonglong2*)&As[kk * 132 + ty * 8 + 4];
            ulonglong2 bP = *(const ulonglong2*)&Bs[kk * 72 + tx * 4];
            ffma2(acc[0][0].u, aA.x, bP.x); ffma2(acc[0][1].u, aA.x, bP.y);
            ffma2(acc[1][0].u, aA.y, bP.x); ffma2(acc[1][1].u, aA.y, bP.y);
            ffma2(acc[2][0].u, aB.x, bP.x); ffma2(acc[2][1].u, aB.x, bP.y);
            ffma2(acc[3][0].u, aB.y, bP.x); ffma2(acc[3][1].u, aB.y, bP.y);
        }
        __syncthreads();
    }
#pragma unroll
    for (int i = 0; i < 4; i++) {
        int m = m0 + ty * 4 + i;
#pragma unroll
        for (int jp = 0; jp < 2; jp++) {
            int n = n0 + tx * 4 + jp * 2;
            float2 v = acc[i][jp].f;
            float o0 = alpha * v.x, o1 = alpha * v.y;
            if (Cin) { o0 += Cin[(size_t)m * ldc + n]; o1 += Cin[(size_t)m * ldc + n + 1]; }
            D[(size_t)m * ldd + n] = o0; D[(size_t)m * ldd + n + 1] = o1;
            if (D2) { D2[(size_t)m * ldd + n] = o0; D2[(size_t)m * ldd + n + 1] = o1; }
        }
    }
}

// ---------------- Newton-Schulz strip: X' = 2X - X (Quu X) over 4 columns --------
// bid < 32; block bid handles cols J = bid*4. One grid barrier per iteration.
// Qs row stride 20 floats = 80 B (16B-aligned for float4 stores).
__device__ __forceinline__ void newton_strip(const float* __restrict__ Xin,
                                             float* __restrict__ Xout, float* sm)
{
    float* Qs = sm;           // [128][20] = 2560
    float* Xs = sm + 2560;    // [128][4]  = 512
    float* Ts = sm + 3072;    // [128][4]  = 512
    const int tid = threadIdx.x;
    const int J = blockIdx.x * 4;
    for (int i = tid; i < 512; i += 256) {
        int r = i >> 2, jj = i & 3;
        Xs[i] = Xin[r * NC + J + jj];
    }
    __syncthreads();
    const int r = tid >> 1, jh = (tid & 1) * 2;
    float t0 = 0.f, t1 = 0.f;
    for (int k0 = 0; k0 < NC; k0 += 16) {
        for (int i = tid; i < 512; i += 256) {
            int rr = i >> 2, q4 = i & 3;
            *(float4*)&Qs[rr * 20 + q4 * 4] =
                *(const float4*)&g_Q[(size_t)(NS + rr) * ND + NS + k0 + q4 * 4];
        }
        __syncthreads();
#pragma unroll
        for (int kk = 0; kk < 16; kk++) {
            float a = Qs[r * 20 + kk];
            t0 = fmaf(a, Xs[(k0 + kk) * 4 + jh], t0);
            t1 = fmaf(a, Xs[(k0 + kk) * 4 + jh + 1], t1);
        }
        __syncthreads();
    }
    Ts[r * 4 + jh] = t0; Ts[r * 4 + jh + 1] = t1;
    __syncthreads();
    float x0 = 0.f, x1 = 0.f;
    for (int k0 = 0; k0 < NC; k0 += 16) {
        for (int i = tid; i < 512; i += 256) {
            int rr = i >> 2, q4 = i & 3;
            *(float4*)&Qs[rr * 20 + q4 * 4] =
                *(const float4*)&Xin[rr * NC + k0 + q4 * 4];
        }
        __syncthreads();
#pragma unroll
        for (int kk = 0; kk < 16; kk++) {
            float a = Qs[r * 20 + kk];
            x0 = fmaf(a, Ts[(k0 + kk) * 4 + jh], x0);
            x1 = fmaf(a, Ts[(k0 + kk) * 4 + jh + 1], x1);
        }
        __syncthreads();
    }
    Xout[r * NC + J + jh]     = 2.f * Xs[r * 4 + jh]     - x0;
    Xout[r * NC + J + jh + 1] = 2.f * Xs[r * 4 + jh + 1] - x1;
}

// ---------------- the persistent kernel -------------------------------------------
__global__ void __launch_bounds__(256, 1) lqr_kernel(
    const float* __restrict__ F, const float* __restrict__ f,
    const float* __restrict__ C, const float* __restrict__ c,
    float* __restrict__ out)
{
    __shared__ __align__(16) float sm[3600];
    __shared__ float red[264];
    const int bid = blockIdx.x, tid = threadIdx.x, nb = gridDim.x;
    float* outK = out;
    float* outk = outK + (size_t)TT * NC * NS;
    float* outV = outk + (size_t)TT * NC;
    float* outv = outV + (size_t)TT * NS * NS;
    float* outc = outv + (size_t)TT * NS;

    // ---- init: Ft = F^T, V = C[:n,:n], v = c[:n], const = 0 ----
    for (int i = bid * 256 + tid; i < ND * NS; i += nb * 256) {
        int a = i / NS, col = i - a * NS;
        g_Ft[i] = F[(size_t)col * ND + a];
    }
    for (int i = bid * 256 + tid; i < NS * NS; i += nb * 256) {
        int r = i >> 9, cq = i & (NS - 1);
        g_V[i] = C[(size_t)r * ND + cq];
    }
    if (bid == nb - 1) {
        for (int i = tid; i < NS; i += 256) g_v[i] = c[i];
        if (tid == 0) g_cst = 0.f;
    }
    gsync();

    int cur = 0;
    for (int s = 0; s < TT; s++) {
        const int t = TT - 1 - s;

        // ---- Phase A: FV = Ft @ V (80 tiles) ; w = V @ f (leftover blocks) ----
        if (bid < 80) {
            gemm64(g_Ft, NS, g_V, NS, nullptr, 0, g_FV, NS, nullptr,
                   NS, 1.f, (bid >> 3) * 64, (bid & 7) * 64, sm);
        } else {
            int row = (bid - 80) * 8 + (tid >> 5);
            int lane = tid & 31;
            if (row < NS) {
                float ssum = 0.f;
                for (int i = lane; i < NS; i += 32) ssum += g_V[row * NS + i] * f[i];
                for (int o = 16; o; o >>= 1) ssum += __shfl_down_sync(~0u, ssum, o);
                if (!lane) g_w[row] = ssum;
            }
        }
        gsync();

        // ---- Phase B: Q = C + FV @ F (100 tiles) ; q = c + FV@f + Ft@v ----
        if (bid < 100) {
            gemm64(g_FV, NS, F, ND, C, ND, g_Q, ND, nullptr,
                   NS, 1.f, (bid / 10) * 64, (bid % 10) * 64, sm);
        } else {
            int gw = (bid - 100) * 8 + (tid >> 5);
            int lane = tid & 31;
            for (int row = gw; row < ND; row += 384) {
                float ssum = 0.f;
                for (int i = lane; i < NS; i += 32)
                    ssum += g_FV[row * NS + i] * f[i] + g_Ft[row * NS + i] * g_v[i];
                for (int o = 16; o; o >>= 1) ssum += __shfl_down_sync(~0u, ssum, o);
                if (!lane) g_q[row] = c[row] + ssum;
            }
        }
        gsync();

        // ---- Phase C0 (s==0): X0 = I / ||Quu||_inf ----
        if (s == 0) {
            if (bid == 0) {
                float m = 0.f;
                if (tid < NC) {
                    float ssum = 0.f;
                    const float* Qr = &g_Q[(size_t)(NS + tid) * ND + NS];
                    for (int j = 0; j < NC; j++) ssum += fabsf(Qr[j]);
                    m = ssum;
                }
                red[tid] = m; __syncthreads();
                for (int st = 128; st; st >>= 1) {
                    if (tid < st) red[tid] = fmaxf(red[tid], red[tid + st]);
                    __syncthreads();
                }
                float inv = 1.f / red[0];
                __syncthreads();
                for (int i = tid; i < NC * NC; i += 256) {
                    int r2 = i >> 7, c2 = i & 127;
                    g_X[0][i] = (r2 == c2) ? inv : 0.f;
                }
            }
            gsync();
        }

        // ---- Phase C: Newton-Schulz iterations (warm-started) ----
        int niter = (s == 0) ? 20 : ((s < 8) ? 4 : 2);
        for (int it = 0; it < niter; it++) {
            if (bid < 32) newton_strip(g_X[cur], g_X[cur ^ 1], sm);
            cur ^= 1;
            gsync();
        }

        // ---- Phase D: K = -X @ Qux (16 tiles); block 16: k, const ----
        if (bid < 16) {
            gemm64(g_X[cur], NC, g_Q + (size_t)NS * ND, ND, nullptr, 0,
                   g_K, NS, outK + (size_t)t * NC * NS,
                   NC, -1.f, (bid >> 3) * 64, (bid & 7) * 64, sm);
        } else if (bid == 16) {
            float* ksh = sm; float* quk = sm + 132;
            float kv = 0.f;
            if (tid < NC) {
                const float* Xr = g_X[cur] + tid * NC;
                for (int j = 0; j < NC; j++) kv += Xr[j] * g_q[NS + j];
                kv = -kv;
                ksh[tid] = kv; g_k[tid] = kv; outk[(size_t)t * NC + tid] = kv;
            }
            __syncthreads();
            if (tid < NC) {
                float qk = 0.f;
                const float* Qr = &g_Q[(size_t)(NS + tid) * ND + NS];
                for (int j = 0; j < NC; j++) qk = fmaf(Qr[j], ksh[j], qk);
                quk[tid] = qk;
            }
            __syncthreads();
            float p1 = 0.f, p2 = 0.f, p3 = 0.f, p4 = 0.f;
            for (int i = tid; i < NC; i += 256) { p1 += ksh[i] * quk[i]; p2 += ksh[i] * g_q[NS + i]; }
            for (int i = tid; i < NS; i += 256) { p3 += f[i] * g_w[i];   p4 += f[i] * g_v[i]; }
            float parts[4] = {p1, p2, p3, p4};
            float res[4];
            for (int qd = 0; qd < 4; qd++) {
                red[tid] = parts[qd]; __syncthreads();
                for (int st = 128; st; st >>= 1) {
                    if (tid < st) red[tid] += red[tid + st];
                    __syncthreads();
                }
                res[qd] = red[0]; __syncthreads();
            }
            if (tid == 0) {
                float cn = g_cst + 0.5f * res[0] + res[1] + 0.5f * res[2] + res[3];
                g_cst = cn;
                outc[t] = cn;
            }
        }
        gsync();

        // ---- Phase E: Vn = Qxx + Qxu @ K (64 tiles); vn = qx + Qxu @ k ----
        if (bid < 64) {
            gemm64(g_Q + NS, ND, g_K, NS, g_Q, ND, g_V, NS,
                   outV + (size_t)t * NS * NS,
                   NC, 1.f, (bid >> 3) * 64, (bid & 7) * 64, sm);
        } else {
            int row = (bid - 64) * 8 + (tid >> 5);
            int lane = tid & 31;
            if (row < NS) {
                float ssum = 0.f;
                for (int i = lane; i < NC; i += 32)
                    ssum += g_Q[(size_t)row * ND + NS + i] * g_k[i];
                for (int o = 16; o; o >>= 1) ssum += __shfl_down_sync(~0u, ssum, o);
                if (!lane) {
                    float val = g_q[row] + ssum;
                    g_v[row] = val;
                    outv[(size_t)t * NS + row] = val;
                }
            }
        }
        gsync();
    }
}

// ---------------- host -------------------------------------------------------------
extern "C" void kernel_launch(void* const* d_in, const int* in_sizes, int n_in,
                              void* d_out, int out_size) {
    (void)in_sizes; (void)n_in; (void)out_size;
    const float* F = (const float*)d_in[0];
    const float* f = (const float*)d_in[1];
    const float* C = (const float*)d_in[2];
    const float* c = (const float*)d_in[3];
    lqr_kernel<<<NBLK, 256>>>(F, f, C, c, (float*)d_out);
}